// round 10
// baseline (speedup 1.0000x reference)
#include <cuda_runtime.h>
#include <math.h>
#include <stdint.h>

// ---------------------------------------------------------------------------
// Problem constants
// ---------------------------------------------------------------------------
constexpr int EMAX  = 119998;
constexpr int NMAX  = 60000;
constexpr int NEMAX = EMAX / 2;   // 59999

constexpr int W_OFF[7] = {0, 425984, 851968, 1015808, 1277952, 1376256, 1507328};
constexpr int W_TOTAL  = 1769472;

// ---------------------------------------------------------------------------
// Scratch (device globals — no allocation allowed in kernel_launch)
// ---------------------------------------------------------------------------
__device__ float g_feats[(size_t)EMAX * 160];
__device__ float g_suv [(size_t)EMAX * 256];
__device__ float g_zbuf[(size_t)EMAX * 256];
__device__ float g_rbuf[(size_t)EMAX * 256];
__device__ float g_rd  [(size_t)EMAX * 256];
__device__ float g_msgA[(size_t)EMAX * 256];
__device__ float g_msgB[(size_t)EMAX * 256];
__device__ float g_aggr[(size_t)NMAX * 256];
__device__ float g_xg  [(size_t)NMAX * 256];
__device__ float g_h1  [(size_t)NMAX * 512];
__device__ float g_xe  [(size_t)NEMAX * 512];
__device__ float g_h2  [(size_t)NEMAX * 512];
__device__ float g_logits[NMAX + NEMAX];
__device__ float g_wrnd[W_TOTAL];

// ---------------------------------------------------------------------------
// TF32 / async helpers
// ---------------------------------------------------------------------------
__device__ __forceinline__ uint32_t f2tf32(float x) {
    uint32_t r;
    asm("cvt.rna.tf32.f32 %0, %1;" : "=r"(r) : "f"(x));
    return r;
}

__device__ __forceinline__ void mma_tf32(float* c, const uint32_t* a,
                                         uint32_t b0, uint32_t b1) {
    asm volatile(
        "mma.sync.aligned.m16n8k8.row.col.f32.tf32.tf32.f32 "
        "{%0,%1,%2,%3}, {%4,%5,%6,%7}, {%8,%9}, {%0,%1,%2,%3};\n"
        : "+f"(c[0]), "+f"(c[1]), "+f"(c[2]), "+f"(c[3])
        : "r"(a[0]), "r"(a[1]), "r"(a[2]), "r"(a[3]),
          "r"(b0), "r"(b1));
}

__device__ __forceinline__ void ldsm_x4(uint32_t* r, uint32_t addr) {
    asm volatile("ldmatrix.sync.aligned.m8n8.x4.shared.b16 {%0,%1,%2,%3}, [%4];\n"
                 : "=r"(r[0]), "=r"(r[1]), "=r"(r[2]), "=r"(r[3]) : "r"(addr));
}

__device__ __forceinline__ void cp_async16(uint32_t saddr, const void* gptr, bool pred) {
    int sz = pred ? 16 : 0;
    asm volatile("cp.async.cg.shared.global [%0], [%1], 16, %2;\n"
                 :: "r"(saddr), "l"(gptr), "r"(sz));
}
__device__ __forceinline__ void cp_commit() {
    asm volatile("cp.async.commit_group;\n" ::: "memory");
}
__device__ __forceinline__ void cp_wait1() {
    asm volatile("cp.async.wait_group 1;\n" ::: "memory");
}

__device__ __forceinline__ float fast_sigmoid(float v) {
    return 1.f / (1.f + __expf(-v));
}
__device__ __forceinline__ float fast_tanh(float v) {
    return 2.f / (1.f + __expf(-2.f * v)) - 1.f;
}

// ---------------------------------------------------------------------------
// 3-stage pipelined TF32 tensor-core GEMM, BM=128 x BN=256 tile, 512 threads.
//   C = epi( [A1|A2] @ [W1|W2]^T + bias ),  K1/K2 compile-time (mult of 32).
//   EPI: 0 sigmoid | 1 relu | 2 (1-z)*su + z*tanh(v)
//        4 z*tanh(v) | 5 like 2 but atomicAdd into C[tgt[m]] (fused seg-sum)
// 16 warps (4m x 4n), warp tile 32x64. A loaded ONCE per row-panel.
// ---------------------------------------------------------------------------
constexpr int SK     = 36;              // 32 + 4 pad (conflict-free ldmatrix)
constexpr int A_U32  = 128 * SK;        // A tile u32 per stage
constexpr int B_U32  = 256 * SK;        // B tile u32 per stage
constexpr int STAGE  = A_U32 + B_U32;   // per stage
constexpr int NSTG   = 3;
constexpr int SMEM_BYTES = NSTG * STAGE * 4;   // 165888

template<int EPI, int K1, int K2>
__global__ void __launch_bounds__(512, 1)
gemm_tc(const float* __restrict__ A1,
        const float* __restrict__ A2,
        const float* __restrict__ W1, int ldw1,
        const float* __restrict__ W2, int ldw2,
        const float* __restrict__ bias,
        const float* __restrict__ zb, const float* __restrict__ sb,
        const int* __restrict__ tgt,
        float* __restrict__ C, int M, int Nout)
{
    extern __shared__ uint32_t smem[];

    const int tid   = threadIdx.x;
    const int lane  = tid & 31;
    const int wid   = tid >> 5;        // 0..15
    const int warpM = wid & 3;         // 4 m-warps  (32 rows each)
    const int warpN = wid >> 2;        // 4 n-warps  (64 cols each)
    const int g     = lane >> 2;
    const int tig   = lane & 3;
    const int m0    = blockIdx.x * 128;
    const int n0    = blockIdx.y * 256;

    const int srow = tid >> 3;         // 0..63
    const int skk  = (tid & 7) << 2;   // 0,4,...,28

    const uint32_t smem_base = (uint32_t)__cvta_generic_to_shared(smem);

    uint32_t offA[2], offB[4];
    {
        const int ra = (lane & 15);
        const int ca = (lane < 16) ? 0 : 4;
#pragma unroll
        for (int mt = 0; mt < 2; mt++)
            offA[mt] = (uint32_t)(((warpM * 32 + mt * 16 + ra) * SK + ca) * 4);
        const int rb = ((lane & 16) >> 1) + (lane & 7);
        const int cb = (lane & 8) ? 4 : 0;
#pragma unroll
        for (int p = 0; p < 4; p++)
            offB[p] = (uint32_t)(((warpN * 64 + p * 16 + rb) * SK + cb) * 4
                                 + A_U32 * 4);
    }

    auto stage_tile = [&](int j) {
        const int kk = (j << 5) + skk;
        const uint32_t abase = smem_base + (uint32_t)((j % NSTG) * STAGE) * 4;
        const uint32_t bbase = abase + (uint32_t)A_U32 * 4;
#pragma unroll
        for (int r = 0; r < 2; r++) {      // A: 128 rows / 64
            const int rr  = srow + r * 64;
            int row = m0 + rr;
            bool ok = row < M;
            if (!ok) row = M - 1;
            const float* src = (kk < K1)
                ? A1 + (size_t)row * K1 + kk
                : A2 + (size_t)row * K2 + (kk - K1);
            cp_async16(abase + (uint32_t)(rr * SK + skk) * 4, src, ok);
        }
#pragma unroll
        for (int r = 0; r < 4; r++) {      // B: 256 rows / 64
            const int rr = srow + r * 64;
            const int nn = n0 + rr;
            const float* wsrc = (kk < K1)
                ? W1 + (size_t)nn * ldw1 + kk
                : W2 + (size_t)nn * ldw2 + (kk - K1);
            cp_async16(bbase + (uint32_t)(rr * SK + skk) * 4, wsrc, true);
        }
        cp_commit();
    };

    float acc[2][8][4];
#pragma unroll
    for (int i = 0; i < 2; i++)
#pragma unroll
        for (int j = 0; j < 8; j++)
#pragma unroll
            for (int q = 0; q < 4; q++) acc[i][j][q] = 0.f;

    constexpr int NK = (K1 + K2) >> 5;
    static_assert(NK >= NSTG, "need at least NSTG k-tiles");

    stage_tile(0);
    stage_tile(1);

#pragma unroll
    for (int it = 0; it < NK; it++) {
        cp_wait1();
        __syncthreads();

        if (it + 2 < NK) stage_tile(it + 2);
        else             cp_commit();

        const uint32_t sbase = smem_base + (uint32_t)((it % NSTG) * STAGE) * 4;

#pragma unroll
        for (int ks = 0; ks < 4; ks++) {
            const uint32_t kof = ks * 32;
            uint32_t af[2][4];
            ldsm_x4(af[0], sbase + offA[0] + kof);
            ldsm_x4(af[1], sbase + offA[1] + kof);
            uint32_t bf[4][4];
#pragma unroll
            for (int p = 0; p < 4; p++)
                ldsm_x4(bf[p], sbase + offB[p] + kof);
#pragma unroll
            for (int mt = 0; mt < 2; mt++)
#pragma unroll
                for (int p = 0; p < 4; p++) {
                    mma_tf32(acc[mt][2*p  ], af[mt], bf[p][0], bf[p][1]);
                    mma_tf32(acc[mt][2*p+1], af[mt], bf[p][2], bf[p][3]);
                }
        }
    }

    // epilogue
#pragma unroll
    for (int nt = 0; nt < 8; nt++) {
        const int col = n0 + warpN * 64 + nt * 8 + tig * 2;
        const float b0 = bias[col];
        const float b1 = bias[col + 1];
#pragma unroll
        for (int mt = 0; mt < 2; mt++) {
#pragma unroll
            for (int h = 0; h < 2; h++) {
                const int m = m0 + warpM * 32 + mt * 16 + g + h * 8;
                if (m >= M) continue;
                float v0 = acc[mt][nt][h * 2 + 0] + b0;
                float v1 = acc[mt][nt][h * 2 + 1] + b1;
                float2 o;
                if (EPI == 0) {
                    o.x = fast_sigmoid(v0);
                    o.y = fast_sigmoid(v1);
                } else if (EPI == 1) {
                    o.x = fmaxf(v0, 0.f);
                    o.y = fmaxf(v1, 0.f);
                } else if (EPI == 4) {
                    const float2 zz = *(const float2*)(zb + (size_t)m * Nout + col);
                    o.x = zz.x * fast_tanh(v0);
                    o.y = zz.y * fast_tanh(v1);
                } else {
                    const float2 zz = *(const float2*)(zb + (size_t)m * Nout + col);
                    const float2 su = *(const float2*)(sb + (size_t)m * Nout + col);
                    o.x = (1.f - zz.x) * su.x + zz.x * fast_tanh(v0);
                    o.y = (1.f - zz.y) * su.y + zz.y * fast_tanh(v1);
                }
                if (EPI == 5) {
                    float* dst = C + (size_t)tgt[m] * Nout + col;
                    atomicAdd(dst,     o.x);
                    atomicAdd(dst + 1, o.y);
                } else {
                    *(float2*)(C + (size_t)m * Nout + col) = o;
                }
            }
        }
    }
}

// ---------------------------------------------------------------------------
// Round all weight matrices to tf32 (rna) into scratch
// ---------------------------------------------------------------------------
__global__ void roundw_k(const float* __restrict__ s0, const float* __restrict__ s1,
                         const float* __restrict__ s2, const float* __restrict__ s3,
                         const float* __restrict__ s4, const float* __restrict__ s5,
                         const float* __restrict__ s6, float* __restrict__ o)
{
    const int cnt[7] = {425984, 425984, 163840, 262144, 98304, 131072, 262144};
    const int off[7] = {0, 425984, 851968, 1015808, 1277952, 1376256, 1507328};
    const float* srcs[7] = {s0, s1, s2, s3, s4, s5, s6};
    int seg = blockIdx.y;
    int i = (blockIdx.x * blockDim.x + threadIdx.x) * 4;
    if (i >= cnt[seg]) return;
    float4 v = *(const float4*)(srcs[seg] + i);
    float4 r;
    r.x = __uint_as_float(f2tf32(v.x));
    r.y = __uint_as_float(f2tf32(v.y));
    r.z = __uint_as_float(f2tf32(v.z));
    r.w = __uint_as_float(f2tf32(v.w));
    *(float4*)(o + off[seg] + i) = r;
}

// ---------------------------------------------------------------------------
// Elementwise / gather kernels
// ---------------------------------------------------------------------------
__global__ void feats_k(const float* __restrict__ x, const float* __restrict__ ea,
                        const int* __restrict__ tgt, float* __restrict__ feats, int E)
{
    int t = blockIdx.x * blockDim.x + threadIdx.x;
    if (t >= E * 40) return;
    int e = t / 40, c = t % 40;
    float4 v;
    if (c < 32) v = *(const float4*)(x + (size_t)tgt[e] * 128 + c * 4);
    else        v = *(const float4*)(ea + (size_t)e * 32 + (c - 32) * 4);
    *(float4*)(feats + (size_t)e * 160 + c * 4) = v;
}

__global__ void gather_s_k(const float* __restrict__ msg, const int* __restrict__ nbr,
                           float* __restrict__ suv, int E)
{
    int t = blockIdx.x * blockDim.x + threadIdx.x;
    if (t >= E * 64) return;
    int e = t >> 6, c = (t & 63) << 2;
    int j0 = nbr[e*3+0], j1 = nbr[e*3+1], j2 = nbr[e*3+2];
    float ax=0.f, ay=0.f, az=0.f, aw=0.f;
    if (j0) { float4 v = *(const float4*)(msg + (size_t)(j0-1)*256 + c); ax+=v.x; ay+=v.y; az+=v.z; aw+=v.w; }
    if (j1) { float4 v = *(const float4*)(msg + (size_t)(j1-1)*256 + c); ax+=v.x; ay+=v.y; az+=v.z; aw+=v.w; }
    if (j2) { float4 v = *(const float4*)(msg + (size_t)(j2-1)*256 + c); ax+=v.x; ay+=v.y; az+=v.z; aw+=v.w; }
    *(float4*)(suv + (size_t)e * 256 + c) = make_float4(ax, ay, az, aw);
}

__global__ void rdash_k(const float* __restrict__ r, const float* __restrict__ msg,
                        const int* __restrict__ nbr, float* __restrict__ rd, int E)
{
    int t = blockIdx.x * blockDim.x + threadIdx.x;
    if (t >= E * 64) return;
    int e = t >> 6, c = (t & 63) << 2;
    int j0 = nbr[e*3+0], j1 = nbr[e*3+1], j2 = nbr[e*3+2];
    float ax=0.f, ay=0.f, az=0.f, aw=0.f;
    if (j0) { size_t o=(size_t)(j0-1)*256+c; float4 rv=*(const float4*)(r+o); float4 mv=*(const float4*)(msg+o);
              ax+=rv.x*mv.x; ay+=rv.y*mv.y; az+=rv.z*mv.z; aw+=rv.w*mv.w; }
    if (j1) { size_t o=(size_t)(j1-1)*256+c; float4 rv=*(const float4*)(r+o); float4 mv=*(const float4*)(msg+o);
              ax+=rv.x*mv.x; ay+=rv.y*mv.y; az+=rv.z*mv.z; aw+=rv.w*mv.w; }
    if (j2) { size_t o=(size_t)(j2-1)*256+c; float4 rv=*(const float4*)(r+o); float4 mv=*(const float4*)(msg+o);
              ax+=rv.x*mv.x; ay+=rv.y*mv.y; az+=rv.z*mv.z; aw+=rv.w*mv.w; }
    *(float4*)(rd + (size_t)e * 256 + c) = make_float4(ax, ay, az, aw);
}

__global__ void xedge_k(const float* __restrict__ xg, const int* __restrict__ ei,
                        float* __restrict__ xe, int E, int Ne)
{
    int t = blockIdx.x * blockDim.x + threadIdx.x;
    if (t >= Ne * 128) return;
    int j = t >> 7, c = t & 127;
    int u = ei[2 * j], v = ei[E + 2 * j];
    int c2 = (c < 64) ? c : (c - 64);
    float4 a = *(const float4*)(xg + (size_t)u * 256 + c2 * 4);
    float4 b = *(const float4*)(xg + (size_t)v * 256 + c2 * 4);
    float4 o;
    if (c < 64) { o.x=fabsf(a.x-b.x); o.y=fabsf(a.y-b.y); o.z=fabsf(a.z-b.z); o.w=fabsf(a.w-b.w); }
    else        { o.x=a.x+b.x; o.y=a.y+b.y; o.z=a.z+b.z; o.w=a.w+b.w; }
    *(float4*)(xe + (size_t)j * 512 + c * 4) = o;
}

__global__ void dot512_k(const float* __restrict__ Hm, const float* __restrict__ w,
                         const float* __restrict__ bptr, float* __restrict__ out, int M)
{
    int row = blockIdx.x;
    if (row >= M) return;
    int t = threadIdx.x;   // 128 threads
    float4 h  = *(const float4*)(Hm + (size_t)row * 512 + t * 4);
    float4 ww = *(const float4*)(w + t * 4);
    float p = h.x*ww.x + h.y*ww.y + h.z*ww.z + h.w*ww.w;
#pragma unroll
    for (int o = 16; o; o >>= 1) p += __shfl_down_sync(0xffffffffu, p, o);
    __shared__ float s[4];
    if ((t & 31) == 0) s[t >> 5] = p;
    __syncthreads();
    if (t == 0) out[row] = s[0] + s[1] + s[2] + s[3] + bptr[0];
}

__global__ void softmax_k(const float* __restrict__ lg, float* __restrict__ out, int T)
{
    __shared__ float red[1024];
    int t = threadIdx.x;
    float mx = -1e30f;
    for (int i = t; i < T; i += 1024) mx = fmaxf(mx, lg[i]);
    red[t] = mx; __syncthreads();
    for (int s = 512; s; s >>= 1) { if (t < s) red[t] = fmaxf(red[t], red[t + s]); __syncthreads(); }
    float m = red[0]; __syncthreads();
    float sm = 0.f;
    for (int i = t; i < T; i += 1024) sm += expf(lg[i] - m);
    red[t] = sm; __syncthreads();
    for (int s = 512; s; s >>= 1) { if (t < s) red[t] += red[t + s]; __syncthreads(); }
    float inv = 1.f / red[0];
    for (int i = t; i < T; i += 1024) out[i] = expf(lg[i] - m) * inv;
}

// ---------------------------------------------------------------------------
// Launch — dual-stream DAG, layer-0 collapsed, fused final segment-sum.
// ---------------------------------------------------------------------------
extern "C" void kernel_launch(void* const* d_in, const int* in_sizes, int n_in,
                              void* d_out, int out_size)
{
    const float* x     = (const float*)d_in[0];
    const float* ea    = (const float*)d_in[1];
    const int*   ei    = (const int*)  d_in[2];
    const int*   nbr   = (const int*)  d_in[3];
    const float* Wz_w  = (const float*)d_in[4];
    const float* Wz_b  = (const float*)d_in[5];
    const float* Wr_w  = (const float*)d_in[6];
    const float* Wr_b  = (const float*)d_in[7];
    const float* W_w   = (const float*)d_in[8];
    const float* U_w   = (const float*)d_in[9];
    const float* U_b   = (const float*)d_in[10];
    const float* mlp_w = (const float*)d_in[11];
    const float* mlp_b = (const float*)d_in[12];
    const float* nc1_w = (const float*)d_in[13];
    const float* nc1_b = (const float*)d_in[14];
    const float* nc2_w = (const float*)d_in[15];
    const float* nc2_b = (const float*)d_in[16];
    const float* ec1_w = (const float*)d_in[17];
    const float* ec1_b = (const float*)d_in[18];
    const float* ec2_w = (const float*)d_in[19];
    const float* ec2_b = (const float*)d_in[20];

    const int n  = in_sizes[0] / 128;
    const int E  = in_sizes[1] / 32;
    const int Ne = E / 2;
    const int* tgt = ei + E;

    float *feats, *suv, *zb, *rb, *rd, *msgA, *msgB, *aggr, *xg, *h1, *xe, *h2, *lg, *wr_;
    cudaGetSymbolAddress((void**)&feats, g_feats);
    cudaGetSymbolAddress((void**)&suv,  g_suv);
    cudaGetSymbolAddress((void**)&zb,   g_zbuf);
    cudaGetSymbolAddress((void**)&rb,   g_rbuf);
    cudaGetSymbolAddress((void**)&rd,   g_rd);
    cudaGetSymbolAddress((void**)&msgA, g_msgA);
    cudaGetSymbolAddress((void**)&msgB, g_msgB);
    cudaGetSymbolAddress((void**)&aggr, g_aggr);
    cudaGetSymbolAddress((void**)&xg,   g_xg);
    cudaGetSymbolAddress((void**)&h1,   g_h1);
    cudaGetSymbolAddress((void**)&xe,   g_xe);
    cudaGetSymbolAddress((void**)&h2,   g_h2);
    cudaGetSymbolAddress((void**)&lg,   g_logits);
    cudaGetSymbolAddress((void**)&wr_,  g_wrnd);

    static cudaStream_t s1 = nullptr;
    static cudaEvent_t  ev[16];
    if (!s1) {
        cudaStreamCreateWithFlags(&s1, cudaStreamNonBlocking);
        for (int i = 0; i < 16; i++)
            cudaEventCreateWithFlags(&ev[i], cudaEventDisableTiming);
    }

    cudaFuncSetAttribute(gemm_tc<0,160,256>, cudaFuncAttributeMaxDynamicSharedMemorySize, SMEM_BYTES);
    cudaFuncSetAttribute(gemm_tc<2,160,256>, cudaFuncAttributeMaxDynamicSharedMemorySize, SMEM_BYTES);
    cudaFuncSetAttribute(gemm_tc<5,160,256>, cudaFuncAttributeMaxDynamicSharedMemorySize, SMEM_BYTES);
    cudaFuncSetAttribute(gemm_tc<0,160,0>,   cudaFuncAttributeMaxDynamicSharedMemorySize, SMEM_BYTES);
    cudaFuncSetAttribute(gemm_tc<4,160,0>,   cudaFuncAttributeMaxDynamicSharedMemorySize, SMEM_BYTES);
    cudaFuncSetAttribute(gemm_tc<1,128,256>, cudaFuncAttributeMaxDynamicSharedMemorySize, SMEM_BYTES);
    cudaFuncSetAttribute(gemm_tc<1,256,0>,   cudaFuncAttributeMaxDynamicSharedMemorySize, SMEM_BYTES);
    cudaFuncSetAttribute(gemm_tc<1,512,0>,   cudaFuncAttributeMaxDynamicSharedMemorySize, SMEM_BYTES);

    const float* rWz  = wr_ + W_OFF[0];
    const float* rWr  = wr_ + W_OFF[1];
    const float* rW   = wr_ + W_OFF[2];
    const float* rU   = wr_ + W_OFF[3];
    const float* rmlp = wr_ + W_OFF[4];
    const float* rnc1 = wr_ + W_OFF[5];
    const float* rec1 = wr_ + W_OFF[6];

    const int TPB = 256;
    const int gE64 = (E * 64 + TPB - 1) / TPB;
    dim3 gg((E + 127) / 128, 1);       // BN=256 covers Nout=256 in one block

    // ---- prologue: fork first, then s1 work ----
    cudaEventRecord(ev[0], 0);
    cudaStreamWaitEvent(s1, ev[0], 0);
    roundw_k<<<dim3(416, 7), 256, 0, s1>>>(Wz_w, Wr_w, W_w, U_w, mlp_w, nc1_w, ec1_w, wr_);
    cudaEventRecord(ev[1], s1);

    feats_k<<<(E * 40 + TPB - 1) / TPB, TPB>>>(x, ea, tgt, feats, E);
    cudaMemsetAsync(aggr, 0, (size_t)n * 256 * sizeof(float));

    cudaStreamWaitEvent(0, ev[1], 0);

    // ---- layer 0 (collapsed) on s0 ----
    gemm_tc<0,160,0><<<gg, 512, SMEM_BYTES>>>(
        feats, nullptr, rWz, 416, nullptr, 0,
        Wz_b, nullptr, nullptr, nullptr, zb, E, 256);
    gemm_tc<4,160,0><<<gg, 512, SMEM_BYTES>>>(
        feats, nullptr, rW, 160, nullptr, 0,
        U_b, zb, nullptr, nullptr, msgA, E, 256);
    cudaEventRecord(ev[2], 0);
    cudaStreamWaitEvent(s1, ev[2], 0);

    float* msg_in  = msgA;
    float* msg_out = msgB;
    int ie = 3;
    for (int l = 1; l < 4; l++) {
        const float* wz = rWz + (size_t)l * 256 * 416;
        const float* wrr= rWr + (size_t)l * 256 * 416;
        const float* ww = rW  + (size_t)l * 256 * 160;
        const float* uw = rU  + (size_t)l * 256 * 256;

        // s1: r-gemm -> rdash
        gemm_tc<0,160,256><<<gg, 512, SMEM_BYTES, s1>>>(
            feats, msg_in, wrr, 416, wrr + 160, 416,
            Wr_b + l * 256, nullptr, nullptr, nullptr, rb, E, 256);
        rdash_k<<<gE64, TPB, 0, s1>>>(rb, msg_in, nbr, rd, E);
        cudaEventRecord(ev[ie], s1);

        // s0: gather -> z-gemm
        gather_s_k<<<gE64, TPB>>>(msg_in, nbr, suv, E);
        gemm_tc<0,160,256><<<gg, 512, SMEM_BYTES>>>(
            feats, suv, wz, 416, wz + 160, 416,
            Wz_b + l * 256, nullptr, nullptr, nullptr, zb, E, 256);

        // join: m-gemm on s0 (last layer fuses segment-sum into aggr)
        cudaStreamWaitEvent(0, ev[ie], 0); ie++;
        if (l < 3) {
            gemm_tc<2,160,256><<<gg, 512, SMEM_BYTES>>>(
                feats, rd, ww, 160, uw, 256,
                U_b + l * 256, zb, suv, nullptr, msg_out, E, 256);
        } else {
            gemm_tc<5,160,256><<<gg, 512, SMEM_BYTES>>>(
                feats, rd, ww, 160, uw, 256,
                U_b + l * 256, zb, suv, tgt, aggr, E, 256);
        }
        cudaEventRecord(ev[ie], 0);
        cudaStreamWaitEvent(s1, ev[ie], 0); ie++;

        float* tmp = msg_in; msg_in = msg_out; msg_out = tmp;
    }

    // ---- readout: node head (s0) || edge head (s1) ----
    dim3 gx((n + 127) / 128, 1);
    gemm_tc<1,128,256><<<gx, 512, SMEM_BYTES>>>(
        x, aggr, rmlp, 384, rmlp + 128, 384,
        mlp_b, nullptr, nullptr, nullptr, xg, n, 256);
    cudaEventRecord(ev[ie], 0);
    cudaStreamWaitEvent(s1, ev[ie], 0); ie++;

    // s1: edge branch
    xedge_k<<<(Ne * 128 + TPB - 1) / TPB, TPB, 0, s1>>>(xg, ei, xe, E, Ne);
    dim3 g2((Ne + 127) / 128, 2);
    gemm_tc<1,512,0><<<g2, 512, SMEM_BYTES, s1>>>(
        xe, nullptr, rec1, 512, nullptr, 0,
        ec1_b, nullptr, nullptr, nullptr, h2, Ne, 512);
    dot512_k<<<Ne, 128, 0, s1>>>(h2, ec2_w, ec2_b, lg + n, Ne);
    cudaEventRecord(ev[ie], s1);

    // s0: node branch
    dim3 g1((n + 127) / 128, 2);
    gemm_tc<1,256,0><<<g1, 512, SMEM_BYTES>>>(
        xg, nullptr, rnc1, 256, nullptr, 0,
        nc1_b, nullptr, nullptr, nullptr, h1, n, 512);
    dot512_k<<<n, 128>>>(h1, nc2_w, nc2_b, lg, n);

    // join + softmax
    cudaStreamWaitEvent(0, ev[ie], 0); ie++;
    softmax_k<<<1, 1024>>>(lg, (float*)d_out, n + Ne);
}

// round 11
// speedup vs baseline: 1.1082x; 1.1082x over previous
#include <cuda_runtime.h>
#include <math.h>
#include <stdint.h>

// ---------------------------------------------------------------------------
// Problem constants
// ---------------------------------------------------------------------------
constexpr int EMAX  = 119998;
constexpr int NMAX  = 60000;
constexpr int NEMAX = EMAX / 2;   // 59999

constexpr int W_OFF[7] = {0, 425984, 851968, 1015808, 1277952, 1376256, 1507328};
constexpr int W_TOTAL  = 1769472;

// ---------------------------------------------------------------------------
// Scratch (device globals — no allocation allowed in kernel_launch)
// ---------------------------------------------------------------------------
__device__ float g_feats[(size_t)EMAX * 160];
__device__ float g_suv [(size_t)EMAX * 256];
__device__ float g_zbuf[(size_t)EMAX * 256];
__device__ float g_rbuf[(size_t)EMAX * 256];
__device__ float g_rd  [(size_t)EMAX * 256];
__device__ float g_msgA[(size_t)EMAX * 256];
__device__ float g_msgB[(size_t)EMAX * 256];
__device__ float g_aggr[(size_t)NMAX * 256];
__device__ float g_xg  [(size_t)NMAX * 256];
__device__ float g_h1  [(size_t)NMAX * 512];
__device__ float g_xe  [(size_t)NEMAX * 512];
__device__ float g_h2  [(size_t)NEMAX * 512];
__device__ float g_logits[NMAX + NEMAX];
__device__ float g_wrnd[W_TOTAL];

// ---------------------------------------------------------------------------
// TF32 / async helpers
// ---------------------------------------------------------------------------
__device__ __forceinline__ uint32_t f2tf32(float x) {
    uint32_t r;
    asm("cvt.rna.tf32.f32 %0, %1;" : "=r"(r) : "f"(x));
    return r;
}

__device__ __forceinline__ void mma_tf32(float* c, const uint32_t* a,
                                         uint32_t b0, uint32_t b1) {
    asm volatile(
        "mma.sync.aligned.m16n8k8.row.col.f32.tf32.tf32.f32 "
        "{%0,%1,%2,%3}, {%4,%5,%6,%7}, {%8,%9}, {%0,%1,%2,%3};\n"
        : "+f"(c[0]), "+f"(c[1]), "+f"(c[2]), "+f"(c[3])
        : "r"(a[0]), "r"(a[1]), "r"(a[2]), "r"(a[3]),
          "r"(b0), "r"(b1));
}

__device__ __forceinline__ void ldsm_x4(uint32_t* r, uint32_t addr) {
    asm volatile("ldmatrix.sync.aligned.m8n8.x4.shared.b16 {%0,%1,%2,%3}, [%4];\n"
                 : "=r"(r[0]), "=r"(r[1]), "=r"(r[2]), "=r"(r[3]) : "r"(addr));
}

__device__ __forceinline__ void cp_async16(uint32_t saddr, const void* gptr, bool pred) {
    int sz = pred ? 16 : 0;
    asm volatile("cp.async.cg.shared.global [%0], [%1], 16, %2;\n"
                 :: "r"(saddr), "l"(gptr), "r"(sz));
}
__device__ __forceinline__ void cp_commit() {
    asm volatile("cp.async.commit_group;\n" ::: "memory");
}
__device__ __forceinline__ void cp_wait1() {
    asm volatile("cp.async.wait_group 1;\n" ::: "memory");
}

__device__ __forceinline__ float fast_sigmoid(float v) {
    return 1.f / (1.f + __expf(-v));
}
__device__ __forceinline__ float fast_tanh(float v) {
    return 2.f / (1.f + __expf(-2.f * v)) - 1.f;
}

// ---------------------------------------------------------------------------
// 3-stage pipelined TF32 tensor-core GEMM, ldmatrix fragments, 1 sync/iter.
//   C = epi( [A1|A2] @ [W1|W2]^T + bias ),  K1/K2 compile-time (mult of 32).
//   EPI: 0 sigmoid | 1 relu | 2 (1-z)*su + z*tanh(v)
//        4 z*tanh(v) | 5 like 2 but atomicAdd into C[tgt[m]] (fused seg-sum)
// BM=BN=128, BK=32, 256 thr, 8 warps (4m x 2n), warp tile 32x64.
// Grid: x = n-block (fastest varying -> row-panel A reuse via L2), y = m-block.
// ---------------------------------------------------------------------------
constexpr int SK    = 36;            // 32 + 4 pad (conflict-free ldmatrix rows)
constexpr int TILE  = 128 * SK;      // u32 per matrix per stage
constexpr int STAGE = 2 * TILE;      // A+B per stage
constexpr int NSTG  = 3;
constexpr int SMEM_BYTES = NSTG * STAGE * 4;   // 110592

template<int EPI, int K1, int K2>
__global__ void __launch_bounds__(256, 2)
gemm_tc(const float* __restrict__ A1,
        const float* __restrict__ A2,
        const float* __restrict__ W1, int ldw1,
        const float* __restrict__ W2, int ldw2,
        const float* __restrict__ bias,
        const float* __restrict__ zb, const float* __restrict__ sb,
        const int* __restrict__ tgt,
        float* __restrict__ C, int M, int Nout)
{
    extern __shared__ uint32_t smem[];

    const int tid   = threadIdx.x;
    const int lane  = tid & 31;
    const int wid   = tid >> 5;
    const int warpM = wid & 3;
    const int warpN = wid >> 2;
    const int g     = lane >> 2;
    const int tig   = lane & 3;
    const int m0    = blockIdx.y * 128;   // m = slow axis
    const int n0    = blockIdx.x * 128;   // n = fast axis (A reuse in L2)

    const int srow = tid >> 3;         // 0..31
    const int skk  = (tid & 7) << 2;   // 0,4,...,28

    const uint32_t smem_base = (uint32_t)__cvta_generic_to_shared(smem);

    uint32_t offA[2], offB[4];
    {
        const int ra = (lane & 15);
        const int ca = (lane < 16) ? 0 : 4;
#pragma unroll
        for (int mt = 0; mt < 2; mt++)
            offA[mt] = (uint32_t)(((warpM * 32 + mt * 16 + ra) * SK + ca) * 4);
        const int rb = ((lane & 16) >> 1) + (lane & 7);
        const int cb = (lane & 8) ? 4 : 0;
#pragma unroll
        for (int p = 0; p < 4; p++)
            offB[p] = (uint32_t)(((warpN * 64 + p * 16 + rb) * SK + cb) * 4
                                 + TILE * 4);
    }

    auto stage_tile = [&](int j) {
        const int kk = (j << 5) + skk;
        const uint32_t abase = smem_base + (uint32_t)((j % NSTG) * STAGE) * 4;
        const uint32_t bbase = abase + (uint32_t)TILE * 4;
#pragma unroll
        for (int r = 0; r < 4; r++) {
            const int rr  = srow + r * 32;
            int row = m0 + rr;
            bool ok = row < M;
            if (!ok) row = M - 1;
            const float* src = (kk < K1)
                ? A1 + (size_t)row * K1 + kk
                : A2 + (size_t)row * K2 + (kk - K1);
            cp_async16(abase + (uint32_t)(rr * SK + skk) * 4, src, ok);
            const int nn = n0 + rr;
            const float* wsrc = (kk < K1)
                ? W1 + (size_t)nn * ldw1 + kk
                : W2 + (size_t)nn * ldw2 + (kk - K1);
            cp_async16(bbase + (uint32_t)(rr * SK + skk) * 4, wsrc, true);
        }
        cp_commit();
    };

    float acc[2][8][4];
#pragma unroll
    for (int i = 0; i < 2; i++)
#pragma unroll
        for (int j = 0; j < 8; j++)
#pragma unroll
            for (int q = 0; q < 4; q++) acc[i][j][q] = 0.f;

    constexpr int NK = (K1 + K2) >> 5;
    static_assert(NK >= NSTG, "need at least NSTG k-tiles");

    stage_tile(0);
    stage_tile(1);

#pragma unroll
    for (int it = 0; it < NK; it++) {
        cp_wait1();
        __syncthreads();

        if (it + 2 < NK) stage_tile(it + 2);
        else             cp_commit();

        const uint32_t sbase = smem_base + (uint32_t)((it % NSTG) * STAGE) * 4;

#pragma unroll
        for (int ks = 0; ks < 4; ks++) {
            const uint32_t kof = ks * 32;
            uint32_t af[2][4];
            ldsm_x4(af[0], sbase + offA[0] + kof);
            ldsm_x4(af[1], sbase + offA[1] + kof);
            uint32_t bf[4][4];
#pragma unroll
            for (int p = 0; p < 4; p++)
                ldsm_x4(bf[p], sbase + offB[p] + kof);
#pragma unroll
            for (int mt = 0; mt < 2; mt++)
#pragma unroll
                for (int p = 0; p < 4; p++) {
                    mma_tf32(acc[mt][2*p  ], af[mt], bf[p][0], bf[p][1]);
                    mma_tf32(acc[mt][2*p+1], af[mt], bf[p][2], bf[p][3]);
                }
        }
    }

    // epilogue
#pragma unroll
    for (int nt = 0; nt < 8; nt++) {
        const int col = n0 + warpN * 64 + nt * 8 + tig * 2;
        const float b0 = bias[col];
        const float b1 = bias[col + 1];
#pragma unroll
        for (int mt = 0; mt < 2; mt++) {
#pragma unroll
            for (int h = 0; h < 2; h++) {
                const int m = m0 + warpM * 32 + mt * 16 + g + h * 8;
                if (m >= M) continue;
                float v0 = acc[mt][nt][h * 2 + 0] + b0;
                float v1 = acc[mt][nt][h * 2 + 1] + b1;
                float2 o;
                if (EPI == 0) {
                    o.x = fast_sigmoid(v0);
                    o.y = fast_sigmoid(v1);
                } else if (EPI == 1) {
                    o.x = fmaxf(v0, 0.f);
                    o.y = fmaxf(v1, 0.f);
                } else if (EPI == 4) {
                    const float2 zz = *(const float2*)(zb + (size_t)m * Nout + col);
                    o.x = zz.x * fast_tanh(v0);
                    o.y = zz.y * fast_tanh(v1);
                } else {
                    const float2 zz = *(const float2*)(zb + (size_t)m * Nout + col);
                    const float2 su = *(const float2*)(sb + (size_t)m * Nout + col);
                    o.x = (1.f - zz.x) * su.x + zz.x * fast_tanh(v0);
                    o.y = (1.f - zz.y) * su.y + zz.y * fast_tanh(v1);
                }
                if (EPI == 5) {
                    float* dst = C + (size_t)tgt[m] * Nout + col;
                    atomicAdd(dst,     o.x);
                    atomicAdd(dst + 1, o.y);
                } else {
                    *(float2*)(C + (size_t)m * Nout + col) = o;
                }
            }
        }
    }
}

// ---------------------------------------------------------------------------
// Round all weight matrices to tf32 (rna) into scratch
// ---------------------------------------------------------------------------
__global__ void roundw_k(const float* __restrict__ s0, const float* __restrict__ s1,
                         const float* __restrict__ s2, const float* __restrict__ s3,
                         const float* __restrict__ s4, const float* __restrict__ s5,
                         const float* __restrict__ s6, float* __restrict__ o)
{
    const int cnt[7] = {425984, 425984, 163840, 262144, 98304, 131072, 262144};
    const int off[7] = {0, 425984, 851968, 1015808, 1277952, 1376256, 1507328};
    const float* srcs[7] = {s0, s1, s2, s3, s4, s5, s6};
    int seg = blockIdx.y;
    int i = (blockIdx.x * blockDim.x + threadIdx.x) * 4;
    if (i >= cnt[seg]) return;
    float4 v = *(const float4*)(srcs[seg] + i);
    float4 r;
    r.x = __uint_as_float(f2tf32(v.x));
    r.y = __uint_as_float(f2tf32(v.y));
    r.z = __uint_as_float(f2tf32(v.z));
    r.w = __uint_as_float(f2tf32(v.w));
    *(float4*)(o + off[seg] + i) = r;
}

// ---------------------------------------------------------------------------
// Elementwise / gather kernels
// ---------------------------------------------------------------------------
__global__ void feats_k(const float* __restrict__ x, const float* __restrict__ ea,
                        const int* __restrict__ tgt, float* __restrict__ feats, int E)
{
    int t = blockIdx.x * blockDim.x + threadIdx.x;
    if (t >= E * 40) return;
    int e = t / 40, c = t % 40;
    float4 v;
    if (c < 32) v = *(const float4*)(x + (size_t)tgt[e] * 128 + c * 4);
    else        v = *(const float4*)(ea + (size_t)e * 32 + (c - 32) * 4);
    *(float4*)(feats + (size_t)e * 160 + c * 4) = v;
}

__global__ void gather_s_k(const float* __restrict__ msg, const int* __restrict__ nbr,
                           float* __restrict__ suv, int E)
{
    int t = blockIdx.x * blockDim.x + threadIdx.x;
    if (t >= E * 64) return;
    int e = t >> 6, c = (t & 63) << 2;
    int j0 = nbr[e*3+0], j1 = nbr[e*3+1], j2 = nbr[e*3+2];
    float ax=0.f, ay=0.f, az=0.f, aw=0.f;
    if (j0) { float4 v = *(const float4*)(msg + (size_t)(j0-1)*256 + c); ax+=v.x; ay+=v.y; az+=v.z; aw+=v.w; }
    if (j1) { float4 v = *(const float4*)(msg + (size_t)(j1-1)*256 + c); ax+=v.x; ay+=v.y; az+=v.z; aw+=v.w; }
    if (j2) { float4 v = *(const float4*)(msg + (size_t)(j2-1)*256 + c); ax+=v.x; ay+=v.y; az+=v.z; aw+=v.w; }
    *(float4*)(suv + (size_t)e * 256 + c) = make_float4(ax, ay, az, aw);
}

__global__ void rdash_k(const float* __restrict__ r, const float* __restrict__ msg,
                        const int* __restrict__ nbr, float* __restrict__ rd, int E)
{
    int t = blockIdx.x * blockDim.x + threadIdx.x;
    if (t >= E * 64) return;
    int e = t >> 6, c = (t & 63) << 2;
    int j0 = nbr[e*3+0], j1 = nbr[e*3+1], j2 = nbr[e*3+2];
    float ax=0.f, ay=0.f, az=0.f, aw=0.f;
    if (j0) { size_t o=(size_t)(j0-1)*256+c; float4 rv=*(const float4*)(r+o); float4 mv=*(const float4*)(msg+o);
              ax+=rv.x*mv.x; ay+=rv.y*mv.y; az+=rv.z*mv.z; aw+=rv.w*mv.w; }
    if (j1) { size_t o=(size_t)(j1-1)*256+c; float4 rv=*(const float4*)(r+o); float4 mv=*(const float4*)(msg+o);
              ax+=rv.x*mv.x; ay+=rv.y*mv.y; az+=rv.z*mv.z; aw+=rv.w*mv.w; }
    if (j2) { size_t o=(size_t)(j2-1)*256+c; float4 rv=*(const float4*)(r+o); float4 mv=*(const float4*)(msg+o);
              ax+=rv.x*mv.x; ay+=rv.y*mv.y; az+=rv.z*mv.z; aw+=rv.w*mv.w; }
    *(float4*)(rd + (size_t)e * 256 + c) = make_float4(ax, ay, az, aw);
}

__global__ void xedge_k(const float* __restrict__ xg, const int* __restrict__ ei,
                        float* __restrict__ xe, int E, int Ne)
{
    int t = blockIdx.x * blockDim.x + threadIdx.x;
    if (t >= Ne * 128) return;
    int j = t >> 7, c = t & 127;
    int u = ei[2 * j], v = ei[E + 2 * j];
    int c2 = (c < 64) ? c : (c - 64);
    float4 a = *(const float4*)(xg + (size_t)u * 256 + c2 * 4);
    float4 b = *(const float4*)(xg + (size_t)v * 256 + c2 * 4);
    float4 o;
    if (c < 64) { o.x=fabsf(a.x-b.x); o.y=fabsf(a.y-b.y); o.z=fabsf(a.z-b.z); o.w=fabsf(a.w-b.w); }
    else        { o.x=a.x+b.x; o.y=a.y+b.y; o.z=a.z+b.z; o.w=a.w+b.w; }
    *(float4*)(xe + (size_t)j * 512 + c * 4) = o;
}

__global__ void dot512_k(const float* __restrict__ Hm, const float* __restrict__ w,
                         const float* __restrict__ bptr, float* __restrict__ out, int M)
{
    int row = blockIdx.x;
    if (row >= M) return;
    int t = threadIdx.x;   // 128 threads
    float4 h  = *(const float4*)(Hm + (size_t)row * 512 + t * 4);
    float4 ww = *(const float4*)(w + t * 4);
    float p = h.x*ww.x + h.y*ww.y + h.z*ww.z + h.w*ww.w;
#pragma unroll
    for (int o = 16; o; o >>= 1) p += __shfl_down_sync(0xffffffffu, p, o);
    __shared__ float s[4];
    if ((t & 31) == 0) s[t >> 5] = p;
    __syncthreads();
    if (t == 0) out[row] = s[0] + s[1] + s[2] + s[3] + bptr[0];
}

__global__ void softmax_k(const float* __restrict__ lg, float* __restrict__ out, int T)
{
    __shared__ float red[1024];
    int t = threadIdx.x;
    float mx = -1e30f;
    for (int i = t; i < T; i += 1024) mx = fmaxf(mx, lg[i]);
    red[t] = mx; __syncthreads();
    for (int s = 512; s; s >>= 1) { if (t < s) red[t] = fmaxf(red[t], red[t + s]); __syncthreads(); }
    float m = red[0]; __syncthreads();
    float sm = 0.f;
    for (int i = t; i < T; i += 1024) sm += expf(lg[i] - m);
    red[t] = sm; __syncthreads();
    for (int s = 512; s; s >>= 1) { if (t < s) red[t] += red[t + s]; __syncthreads(); }
    float inv = 1.f / red[0];
    for (int i = t; i < T; i += 1024) out[i] = expf(lg[i] - m) * inv;
}

// ---------------------------------------------------------------------------
// Launch — dual-stream DAG, layer-0 collapsed, fused final segment-sum.
// Grid order: n-block fastest (x), m-block slow (y) -> A panel L2 reuse.
// ---------------------------------------------------------------------------
extern "C" void kernel_launch(void* const* d_in, const int* in_sizes, int n_in,
                              void* d_out, int out_size)
{
    const float* x     = (const float*)d_in[0];
    const float* ea    = (const float*)d_in[1];
    const int*   ei    = (const int*)  d_in[2];
    const int*   nbr   = (const int*)  d_in[3];
    const float* Wz_w  = (const float*)d_in[4];
    const float* Wz_b  = (const float*)d_in[5];
    const float* Wr_w  = (const float*)d_in[6];
    const float* Wr_b  = (const float*)d_in[7];
    const float* W_w   = (const float*)d_in[8];
    const float* U_w   = (const float*)d_in[9];
    const float* U_b   = (const float*)d_in[10];
    const float* mlp_w = (const float*)d_in[11];
    const float* mlp_b = (const float*)d_in[12];
    const float* nc1_w = (const float*)d_in[13];
    const float* nc1_b = (const float*)d_in[14];
    const float* nc2_w = (const float*)d_in[15];
    const float* nc2_b = (const float*)d_in[16];
    const float* ec1_w = (const float*)d_in[17];
    const float* ec1_b = (const float*)d_in[18];
    const float* ec2_w = (const float*)d_in[19];
    const float* ec2_b = (const float*)d_in[20];

    const int n  = in_sizes[0] / 128;
    const int E  = in_sizes[1] / 32;
    const int Ne = E / 2;
    const int* tgt = ei + E;

    float *feats, *suv, *zb, *rb, *rd, *msgA, *msgB, *aggr, *xg, *h1, *xe, *h2, *lg, *wr_;
    cudaGetSymbolAddress((void**)&feats, g_feats);
    cudaGetSymbolAddress((void**)&suv,  g_suv);
    cudaGetSymbolAddress((void**)&zb,   g_zbuf);
    cudaGetSymbolAddress((void**)&rb,   g_rbuf);
    cudaGetSymbolAddress((void**)&rd,   g_rd);
    cudaGetSymbolAddress((void**)&msgA, g_msgA);
    cudaGetSymbolAddress((void**)&msgB, g_msgB);
    cudaGetSymbolAddress((void**)&aggr, g_aggr);
    cudaGetSymbolAddress((void**)&xg,   g_xg);
    cudaGetSymbolAddress((void**)&h1,   g_h1);
    cudaGetSymbolAddress((void**)&xe,   g_xe);
    cudaGetSymbolAddress((void**)&h2,   g_h2);
    cudaGetSymbolAddress((void**)&lg,   g_logits);
    cudaGetSymbolAddress((void**)&wr_,  g_wrnd);

    static cudaStream_t s1 = nullptr;
    static cudaEvent_t  ev[16];
    if (!s1) {
        cudaStreamCreateWithFlags(&s1, cudaStreamNonBlocking);
        for (int i = 0; i < 16; i++)
            cudaEventCreateWithFlags(&ev[i], cudaEventDisableTiming);
    }

    cudaFuncSetAttribute(gemm_tc<0,160,256>, cudaFuncAttributeMaxDynamicSharedMemorySize, SMEM_BYTES);
    cudaFuncSetAttribute(gemm_tc<2,160,256>, cudaFuncAttributeMaxDynamicSharedMemorySize, SMEM_BYTES);
    cudaFuncSetAttribute(gemm_tc<5,160,256>, cudaFuncAttributeMaxDynamicSharedMemorySize, SMEM_BYTES);
    cudaFuncSetAttribute(gemm_tc<0,160,0>,   cudaFuncAttributeMaxDynamicSharedMemorySize, SMEM_BYTES);
    cudaFuncSetAttribute(gemm_tc<4,160,0>,   cudaFuncAttributeMaxDynamicSharedMemorySize, SMEM_BYTES);
    cudaFuncSetAttribute(gemm_tc<1,128,256>, cudaFuncAttributeMaxDynamicSharedMemorySize, SMEM_BYTES);
    cudaFuncSetAttribute(gemm_tc<1,256,0>,   cudaFuncAttributeMaxDynamicSharedMemorySize, SMEM_BYTES);
    cudaFuncSetAttribute(gemm_tc<1,512,0>,   cudaFuncAttributeMaxDynamicSharedMemorySize, SMEM_BYTES);

    const float* rWz  = wr_ + W_OFF[0];
    const float* rWr  = wr_ + W_OFF[1];
    const float* rW   = wr_ + W_OFF[2];
    const float* rU   = wr_ + W_OFF[3];
    const float* rmlp = wr_ + W_OFF[4];
    const float* rnc1 = wr_ + W_OFF[5];
    const float* rec1 = wr_ + W_OFF[6];

    const int TPB = 256;
    const int gE64 = (E * 64 + TPB - 1) / TPB;
    dim3 gg(2, (E + 127) / 128);      // x = n-block (fast), y = m-block

    // ---- prologue: fork first, then s1 work ----
    cudaEventRecord(ev[0], 0);
    cudaStreamWaitEvent(s1, ev[0], 0);
    roundw_k<<<dim3(416, 7), 256, 0, s1>>>(Wz_w, Wr_w, W_w, U_w, mlp_w, nc1_w, ec1_w, wr_);
    cudaEventRecord(ev[1], s1);

    feats_k<<<(E * 40 + TPB - 1) / TPB, TPB>>>(x, ea, tgt, feats, E);
    cudaMemsetAsync(aggr, 0, (size_t)n * 256 * sizeof(float));

    cudaStreamWaitEvent(0, ev[1], 0);

    // ---- layer 0 (collapsed) on s0 ----
    gemm_tc<0,160,0><<<gg, 256, SMEM_BYTES>>>(
        feats, nullptr, rWz, 416, nullptr, 0,
        Wz_b, nullptr, nullptr, nullptr, zb, E, 256);
    gemm_tc<4,160,0><<<gg, 256, SMEM_BYTES>>>(
        feats, nullptr, rW, 160, nullptr, 0,
        U_b, zb, nullptr, nullptr, msgA, E, 256);
    cudaEventRecord(ev[2], 0);
    cudaStreamWaitEvent(s1, ev[2], 0);

    float* msg_in  = msgA;
    float* msg_out = msgB;
    int ie = 3;
    for (int l = 1; l < 4; l++) {
        const float* wz = rWz + (size_t)l * 256 * 416;
        const float* wrr= rWr + (size_t)l * 256 * 416;
        const float* ww = rW  + (size_t)l * 256 * 160;
        const float* uw = rU  + (size_t)l * 256 * 256;

        // s1: r-gemm -> rdash
        gemm_tc<0,160,256><<<gg, 256, SMEM_BYTES, s1>>>(
            feats, msg_in, wrr, 416, wrr + 160, 416,
            Wr_b + l * 256, nullptr, nullptr, nullptr, rb, E, 256);
        rdash_k<<<gE64, TPB, 0, s1>>>(rb, msg_in, nbr, rd, E);
        cudaEventRecord(ev[ie], s1);

        // s0: gather -> z-gemm
        gather_s_k<<<gE64, TPB>>>(msg_in, nbr, suv, E);
        gemm_tc<0,160,256><<<gg, 256, SMEM_BYTES>>>(
            feats, suv, wz, 416, wz + 160, 416,
            Wz_b + l * 256, nullptr, nullptr, nullptr, zb, E, 256);

        // join: m-gemm on s0 (last layer fuses segment-sum into aggr)
        cudaStreamWaitEvent(0, ev[ie], 0); ie++;
        if (l < 3) {
            gemm_tc<2,160,256><<<gg, 256, SMEM_BYTES>>>(
                feats, rd, ww, 160, uw, 256,
                U_b + l * 256, zb, suv, nullptr, msg_out, E, 256);
        } else {
            gemm_tc<5,160,256><<<gg, 256, SMEM_BYTES>>>(
                feats, rd, ww, 160, uw, 256,
                U_b + l * 256, zb, suv, tgt, aggr, E, 256);
        }
        cudaEventRecord(ev[ie], 0);
        cudaStreamWaitEvent(s1, ev[ie], 0); ie++;

        float* tmp = msg_in; msg_in = msg_out; msg_out = tmp;
    }

    // ---- readout: node head (s0) || edge head (s1) ----
    dim3 gx(2, (n + 127) / 128);
    gemm_tc<1,128,256><<<gx, 256, SMEM_BYTES>>>(
        x, aggr, rmlp, 384, rmlp + 128, 384,
        mlp_b, nullptr, nullptr, nullptr, xg, n, 256);
    cudaEventRecord(ev[ie], 0);
    cudaStreamWaitEvent(s1, ev[ie], 0); ie++;

    // s1: edge branch
    xedge_k<<<(Ne * 128 + TPB - 1) / TPB, TPB, 0, s1>>>(xg, ei, xe, E, Ne);
    dim3 g2(4, (Ne + 127) / 128);
    gemm_tc<1,512,0><<<g2, 256, SMEM_BYTES, s1>>>(
        xe, nullptr, rec1, 512, nullptr, 0,
        ec1_b, nullptr, nullptr, nullptr, h2, Ne, 512);
    dot512_k<<<Ne, 128, 0, s1>>>(h2, ec2_w, ec2_b, lg + n, Ne);
    cudaEventRecord(ev[ie], s1);

    // s0: node branch
    dim3 g1(4, (n + 127) / 128);
    gemm_tc<1,256,0><<<g1, 256, SMEM_BYTES>>>(
        xg, nullptr, rnc1, 256, nullptr, 0,
        nc1_b, nullptr, nullptr, nullptr, h1, n, 512);
    dot512_k<<<n, 128>>>(h1, nc2_w, nc2_b, lg, n);

    // join + softmax
    cudaStreamWaitEvent(0, ev[ie], 0); ie++;
    softmax_k<<<1, 1024>>>(lg, (float*)d_out, n + Ne);
}

// round 12
// speedup vs baseline: 1.1660x; 1.0521x over previous
#include <cuda_runtime.h>
#include <math.h>
#include <stdint.h>

// ---------------------------------------------------------------------------
// Problem constants
// ---------------------------------------------------------------------------
constexpr int EMAX  = 119998;
constexpr int NMAX  = 60000;
constexpr int NEMAX = EMAX / 2;   // 59999

constexpr int W_OFF[7] = {0, 425984, 851968, 1015808, 1277952, 1376256, 1507328};
constexpr int W_TOTAL  = 1769472;

// ---------------------------------------------------------------------------
// Scratch (device globals — no allocation allowed in kernel_launch)
// ---------------------------------------------------------------------------
__device__ float g_feats[(size_t)EMAX * 160];
__device__ float g_suv [(size_t)EMAX * 256];
__device__ float g_zbuf[(size_t)EMAX * 256];
__device__ float g_rbuf[(size_t)EMAX * 256];
__device__ float g_rd  [(size_t)EMAX * 256];
__device__ float g_msgA[(size_t)EMAX * 256];
__device__ float g_msgB[(size_t)EMAX * 256];
__device__ float g_aggr[(size_t)NMAX * 256];
__device__ float g_xg  [(size_t)NMAX * 256];
__device__ float g_xe  [(size_t)NEMAX * 512];
__device__ float g_logits[NMAX + NEMAX];
__device__ float g_wrnd[W_TOTAL];
__device__ float g_wl0[512 * 160];
__device__ float g_bl0[512];

// ---------------------------------------------------------------------------
// TF32 / async helpers
// ---------------------------------------------------------------------------
__device__ __forceinline__ uint32_t f2tf32(float x) {
    uint32_t r;
    asm("cvt.rna.tf32.f32 %0, %1;" : "=r"(r) : "f"(x));
    return r;
}

__device__ __forceinline__ void mma_tf32(float* c, const uint32_t* a,
                                         uint32_t b0, uint32_t b1) {
    asm volatile(
        "mma.sync.aligned.m16n8k8.row.col.f32.tf32.tf32.f32 "
        "{%0,%1,%2,%3}, {%4,%5,%6,%7}, {%8,%9}, {%0,%1,%2,%3};\n"
        : "+f"(c[0]), "+f"(c[1]), "+f"(c[2]), "+f"(c[3])
        : "r"(a[0]), "r"(a[1]), "r"(a[2]), "r"(a[3]),
          "r"(b0), "r"(b1));
}

__device__ __forceinline__ void ldsm_x4(uint32_t* r, uint32_t addr) {
    asm volatile("ldmatrix.sync.aligned.m8n8.x4.shared.b16 {%0,%1,%2,%3}, [%4];\n"
                 : "=r"(r[0]), "=r"(r[1]), "=r"(r[2]), "=r"(r[3]) : "r"(addr));
}

__device__ __forceinline__ void cp_async16(uint32_t saddr, const void* gptr, bool pred) {
    int sz = pred ? 16 : 0;
    asm volatile("cp.async.cg.shared.global [%0], [%1], 16, %2;\n"
                 :: "r"(saddr), "l"(gptr), "r"(sz));
}
__device__ __forceinline__ void cp_commit() {
    asm volatile("cp.async.commit_group;\n" ::: "memory");
}
__device__ __forceinline__ void cp_wait1() {
    asm volatile("cp.async.wait_group 1;\n" ::: "memory");
}

__device__ __forceinline__ float fast_sigmoid(float v) {
    return 1.f / (1.f + __expf(-v));
}
__device__ __forceinline__ float fast_tanh(float v) {
    return 2.f / (1.f + __expf(-2.f * v)) - 1.f;
}

// ---------------------------------------------------------------------------
// 3-stage pipelined TF32 tensor-core GEMM, ldmatrix fragments, 1 sync/iter.
//   C = epi( [A1|A2] @ [W1|W2]^T + bias ),  K1/K2 compile-time (mult of 32).
//   EPI: 0 sigmoid | 1 relu | 2 (1-z)*su + z*tanh(v)
//        5 like 2 but atomicAdd into C[tgt[m]]   (fused segment-sum)
//        6 head: atomicAdd(C[m], sum relu(v)*sb[col])  (fused 512->1 dot)
//        7 layer-0 fused: interleaved cols (2j=z_pre, 2j+1=m_pre),
//          C[m*256 + col/2] = sigmoid(v0)*tanh(v1)
// BM=BN=128, BK=32, 256 thr, 8 warps (4m x 2n), warp tile 32x64.
// Grid: x = n-block (fast, A L2 reuse), y = m-block.
// ---------------------------------------------------------------------------
constexpr int SK    = 36;
constexpr int TILE  = 128 * SK;
constexpr int STAGE = 2 * TILE;
constexpr int NSTG  = 3;
constexpr int SMEM_BYTES = NSTG * STAGE * 4;   // 110592

template<int EPI, int K1, int K2>
__global__ void __launch_bounds__(256, 2)
gemm_tc(const float* __restrict__ A1,
        const float* __restrict__ A2,
        const float* __restrict__ W1, int ldw1,
        const float* __restrict__ W2, int ldw2,
        const float* __restrict__ bias,
        const float* __restrict__ zb, const float* __restrict__ sb,
        const int* __restrict__ tgt,
        float* __restrict__ C, int M, int Nout)
{
    extern __shared__ uint32_t smem[];

    const int tid   = threadIdx.x;
    const int lane  = tid & 31;
    const int wid   = tid >> 5;
    const int warpM = wid & 3;
    const int warpN = wid >> 2;
    const int g     = lane >> 2;
    const int tig   = lane & 3;
    const int m0    = blockIdx.y * 128;
    const int n0    = blockIdx.x * 128;

    const int srow = tid >> 3;
    const int skk  = (tid & 7) << 2;

    const uint32_t smem_base = (uint32_t)__cvta_generic_to_shared(smem);

    uint32_t offA[2], offB[4];
    {
        const int ra = (lane & 15);
        const int ca = (lane < 16) ? 0 : 4;
#pragma unroll
        for (int mt = 0; mt < 2; mt++)
            offA[mt] = (uint32_t)(((warpM * 32 + mt * 16 + ra) * SK + ca) * 4);
        const int rb = ((lane & 16) >> 1) + (lane & 7);
        const int cb = (lane & 8) ? 4 : 0;
#pragma unroll
        for (int p = 0; p < 4; p++)
            offB[p] = (uint32_t)(((warpN * 64 + p * 16 + rb) * SK + cb) * 4
                                 + TILE * 4);
    }

    auto stage_tile = [&](int j) {
        const int kk = (j << 5) + skk;
        const uint32_t abase = smem_base + (uint32_t)((j % NSTG) * STAGE) * 4;
        const uint32_t bbase = abase + (uint32_t)TILE * 4;
#pragma unroll
        for (int r = 0; r < 4; r++) {
            const int rr  = srow + r * 32;
            int row = m0 + rr;
            bool ok = row < M;
            if (!ok) row = M - 1;
            const float* src = (kk < K1)
                ? A1 + (size_t)row * K1 + kk
                : A2 + (size_t)row * K2 + (kk - K1);
            cp_async16(abase + (uint32_t)(rr * SK + skk) * 4, src, ok);
            const int nn = n0 + rr;
            const float* wsrc = (kk < K1)
                ? W1 + (size_t)nn * ldw1 + kk
                : W2 + (size_t)nn * ldw2 + (kk - K1);
            cp_async16(bbase + (uint32_t)(rr * SK + skk) * 4, wsrc, true);
        }
        cp_commit();
    };

    float acc[2][8][4];
#pragma unroll
    for (int i = 0; i < 2; i++)
#pragma unroll
        for (int j = 0; j < 8; j++)
#pragma unroll
            for (int q = 0; q < 4; q++) acc[i][j][q] = 0.f;

    constexpr int NK = (K1 + K2) >> 5;
    static_assert(NK >= NSTG, "need at least NSTG k-tiles");

    stage_tile(0);
    stage_tile(1);

#pragma unroll
    for (int it = 0; it < NK; it++) {
        cp_wait1();
        __syncthreads();

        if (it + 2 < NK) stage_tile(it + 2);
        else             cp_commit();

        const uint32_t sbase = smem_base + (uint32_t)((it % NSTG) * STAGE) * 4;

#pragma unroll
        for (int ks = 0; ks < 4; ks++) {
            const uint32_t kof = ks * 32;
            uint32_t af[2][4];
            ldsm_x4(af[0], sbase + offA[0] + kof);
            ldsm_x4(af[1], sbase + offA[1] + kof);
            uint32_t bf[4][4];
#pragma unroll
            for (int p = 0; p < 4; p++)
                ldsm_x4(bf[p], sbase + offB[p] + kof);
#pragma unroll
            for (int mt = 0; mt < 2; mt++)
#pragma unroll
                for (int p = 0; p < 4; p++) {
                    mma_tf32(acc[mt][2*p  ], af[mt], bf[p][0], bf[p][1]);
                    mma_tf32(acc[mt][2*p+1], af[mt], bf[p][2], bf[p][3]);
                }
        }
    }

    if (EPI == 6) {
        // fused 512->1 head: partial dot of relu(hidden) with sb, per row
        float pr[2][2] = {{0.f, 0.f}, {0.f, 0.f}};
#pragma unroll
        for (int nt = 0; nt < 8; nt++) {
            const int col = n0 + warpN * 64 + nt * 8 + tig * 2;
            const float b0 = bias[col],  b1 = bias[col + 1];
            const float w0 = sb[col],    w1 = sb[col + 1];
#pragma unroll
            for (int mt = 0; mt < 2; mt++)
#pragma unroll
                for (int h = 0; h < 2; h++) {
                    float v0 = acc[mt][nt][h * 2 + 0] + b0;
                    float v1 = acc[mt][nt][h * 2 + 1] + b1;
                    pr[mt][h] += fmaxf(v0, 0.f) * w0 + fmaxf(v1, 0.f) * w1;
                }
        }
#pragma unroll
        for (int mt = 0; mt < 2; mt++)
#pragma unroll
            for (int h = 0; h < 2; h++) {
                pr[mt][h] += __shfl_xor_sync(0xffffffffu, pr[mt][h], 1);
                pr[mt][h] += __shfl_xor_sync(0xffffffffu, pr[mt][h], 2);
            }
        __syncthreads();
        float* red = (float*)smem;          // 128 rows x 2 warpN
        if (tig == 0) {
#pragma unroll
            for (int mt = 0; mt < 2; mt++)
#pragma unroll
                for (int h = 0; h < 2; h++) {
                    int row = warpM * 32 + mt * 16 + g + h * 8;
                    red[row * 2 + warpN] = pr[mt][h];
                }
        }
        __syncthreads();
        if (warpN == 0 && tig == 0) {
#pragma unroll
            for (int mt = 0; mt < 2; mt++)
#pragma unroll
                for (int h = 0; h < 2; h++) {
                    int row = warpM * 32 + mt * 16 + g + h * 8;
                    int m = m0 + row;
                    if (m < M)
                        atomicAdd(&C[m], red[row * 2] + red[row * 2 + 1]);
                }
        }
        return;
    }

    // element-wise epilogues
#pragma unroll
    for (int nt = 0; nt < 8; nt++) {
        const int col = n0 + warpN * 64 + nt * 8 + tig * 2;
        const float b0 = bias[col];
        const float b1 = bias[col + 1];
#pragma unroll
        for (int mt = 0; mt < 2; mt++) {
#pragma unroll
            for (int h = 0; h < 2; h++) {
                const int m = m0 + warpM * 32 + mt * 16 + g + h * 8;
                if (m >= M) continue;
                float v0 = acc[mt][nt][h * 2 + 0] + b0;
                float v1 = acc[mt][nt][h * 2 + 1] + b1;
                if (EPI == 7) {
                    C[(size_t)m * 256 + (col >> 1)] =
                        fast_sigmoid(v0) * fast_tanh(v1);
                    continue;
                }
                float2 o;
                if (EPI == 0) {
                    o.x = fast_sigmoid(v0);
                    o.y = fast_sigmoid(v1);
                } else if (EPI == 1) {
                    o.x = fmaxf(v0, 0.f);
                    o.y = fmaxf(v1, 0.f);
                } else {
                    const float2 zz = *(const float2*)(zb + (size_t)m * Nout + col);
                    const float2 su = *(const float2*)(sb + (size_t)m * Nout + col);
                    o.x = (1.f - zz.x) * su.x + zz.x * fast_tanh(v0);
                    o.y = (1.f - zz.y) * su.y + zz.y * fast_tanh(v1);
                }
                if (EPI == 5) {
                    float* dst = C + (size_t)tgt[m] * Nout + col;
                    atomicAdd(dst,     o.x);
                    atomicAdd(dst + 1, o.y);
                } else {
                    *(float2*)(C + (size_t)m * Nout + col) = o;
                }
            }
        }
    }
}

// ---------------------------------------------------------------------------
// Round all weight matrices to tf32 (rna) into scratch
// ---------------------------------------------------------------------------
__global__ void roundw_k(const float* __restrict__ s0, const float* __restrict__ s1,
                         const float* __restrict__ s2, const float* __restrict__ s3,
                         const float* __restrict__ s4, const float* __restrict__ s5,
                         const float* __restrict__ s6, float* __restrict__ o)
{
    const int cnt[7] = {425984, 425984, 163840, 262144, 98304, 131072, 262144};
    const int off[7] = {0, 425984, 851968, 1015808, 1277952, 1376256, 1507328};
    const float* srcs[7] = {s0, s1, s2, s3, s4, s5, s6};
    int seg = blockIdx.y;
    int i = (blockIdx.x * blockDim.x + threadIdx.x) * 4;
    if (i >= cnt[seg]) return;
    float4 v = *(const float4*)(srcs[seg] + i);
    float4 r;
    r.x = __uint_as_float(f2tf32(v.x));
    r.y = __uint_as_float(f2tf32(v.y));
    r.z = __uint_as_float(f2tf32(v.z));
    r.w = __uint_as_float(f2tf32(v.w));
    *(float4*)(o + off[seg] + i) = r;
}

// Interleave layer-0 weights: wo row 2j = Wz_l0[j][0:160], row 2j+1 = W_l0[j].
// bo[2j] = Wz_b[j], bo[2j+1] = U_b[j].
__global__ void il0_k(const float* __restrict__ Wz, const float* __restrict__ Ww,
                      const float* __restrict__ Wzb, const float* __restrict__ Ub,
                      float* __restrict__ wo, float* __restrict__ bo)
{
    int t = blockIdx.x * blockDim.x + threadIdx.x;
    if (t < 512) bo[t] = (t & 1) ? Ub[t >> 1] : Wzb[t >> 1];
    if (t >= 512 * 40) return;
    int row = t / 40, c = (t % 40) * 4;
    const float* src = (row & 1)
        ? Ww + (size_t)(row >> 1) * 160 + c
        : Wz + (size_t)(row >> 1) * 416 + c;
    float4 v = *(const float4*)src;
    float4 r;
    r.x = __uint_as_float(f2tf32(v.x));
    r.y = __uint_as_float(f2tf32(v.y));
    r.z = __uint_as_float(f2tf32(v.z));
    r.w = __uint_as_float(f2tf32(v.w));
    *(float4*)(wo + row * 160 + c) = r;
}

// Initialize logits with head-2 biases (EPI 6 atomically accumulates on top).
__global__ void initlg_k(float* __restrict__ lg, const float* __restrict__ nb,
                         const float* __restrict__ eb, int n, int T)
{
    int t = blockIdx.x * blockDim.x + threadIdx.x;
    if (t >= T) return;
    lg[t] = (t < n) ? nb[0] : eb[0];
}

// ---------------------------------------------------------------------------
// Elementwise / gather kernels
// ---------------------------------------------------------------------------
__global__ void feats_k(const float* __restrict__ x, const float* __restrict__ ea,
                        const int* __restrict__ tgt, float* __restrict__ feats, int E)
{
    int t = blockIdx.x * blockDim.x + threadIdx.x;
    if (t >= E * 40) return;
    int e = t / 40, c = t % 40;
    float4 v;
    if (c < 32) v = *(const float4*)(x + (size_t)tgt[e] * 128 + c * 4);
    else        v = *(const float4*)(ea + (size_t)e * 32 + (c - 32) * 4);
    *(float4*)(feats + (size_t)e * 160 + c * 4) = v;
}

__global__ void gather_s_k(const float* __restrict__ msg, const int* __restrict__ nbr,
                           float* __restrict__ suv, int E)
{
    int t = blockIdx.x * blockDim.x + threadIdx.x;
    if (t >= E * 64) return;
    int e = t >> 6, c = (t & 63) << 2;
    int j0 = nbr[e*3+0], j1 = nbr[e*3+1], j2 = nbr[e*3+2];
    float ax=0.f, ay=0.f, az=0.f, aw=0.f;
    if (j0) { float4 v = *(const float4*)(msg + (size_t)(j0-1)*256 + c); ax+=v.x; ay+=v.y; az+=v.z; aw+=v.w; }
    if (j1) { float4 v = *(const float4*)(msg + (size_t)(j1-1)*256 + c); ax+=v.x; ay+=v.y; az+=v.z; aw+=v.w; }
    if (j2) { float4 v = *(const float4*)(msg + (size_t)(j2-1)*256 + c); ax+=v.x; ay+=v.y; az+=v.z; aw+=v.w; }
    *(float4*)(suv + (size_t)e * 256 + c) = make_float4(ax, ay, az, aw);
}

__global__ void rdash_k(const float* __restrict__ r, const float* __restrict__ msg,
                        const int* __restrict__ nbr, float* __restrict__ rd, int E)
{
    int t = blockIdx.x * blockDim.x + threadIdx.x;
    if (t >= E * 64) return;
    int e = t >> 6, c = (t & 63) << 2;
    int j0 = nbr[e*3+0], j1 = nbr[e*3+1], j2 = nbr[e*3+2];
    float ax=0.f, ay=0.f, az=0.f, aw=0.f;
    if (j0) { size_t o=(size_t)(j0-1)*256+c; float4 rv=*(const float4*)(r+o); float4 mv=*(const float4*)(msg+o);
              ax+=rv.x*mv.x; ay+=rv.y*mv.y; az+=rv.z*mv.z; aw+=rv.w*mv.w; }
    if (j1) { size_t o=(size_t)(j1-1)*256+c; float4 rv=*(const float4*)(r+o); float4 mv=*(const float4*)(msg+o);
              ax+=rv.x*mv.x; ay+=rv.y*mv.y; az+=rv.z*mv.z; aw+=rv.w*mv.w; }
    if (j2) { size_t o=(size_t)(j2-1)*256+c; float4 rv=*(const float4*)(r+o); float4 mv=*(const float4*)(msg+o);
              ax+=rv.x*mv.x; ay+=rv.y*mv.y; az+=rv.z*mv.z; aw+=rv.w*mv.w; }
    *(float4*)(rd + (size_t)e * 256 + c) = make_float4(ax, ay, az, aw);
}

__global__ void xedge_k(const float* __restrict__ xg, const int* __restrict__ ei,
                        float* __restrict__ xe, int E, int Ne)
{
    int t = blockIdx.x * blockDim.x + threadIdx.x;
    if (t >= Ne * 128) return;
    int j = t >> 7, c = t & 127;
    int u = ei[2 * j], v = ei[E + 2 * j];
    int c2 = (c < 64) ? c : (c - 64);
    float4 a = *(const float4*)(xg + (size_t)u * 256 + c2 * 4);
    float4 b = *(const float4*)(xg + (size_t)v * 256 + c2 * 4);
    float4 o;
    if (c < 64) { o.x=fabsf(a.x-b.x); o.y=fabsf(a.y-b.y); o.z=fabsf(a.z-b.z); o.w=fabsf(a.w-b.w); }
    else        { o.x=a.x+b.x; o.y=a.y+b.y; o.z=a.z+b.z; o.w=a.w+b.w; }
    *(float4*)(xe + (size_t)j * 512 + c * 4) = o;
}

__global__ void softmax_k(const float* __restrict__ lg, float* __restrict__ out, int T)
{
    __shared__ float red[1024];
    int t = threadIdx.x;
    float mx = -1e30f;
    for (int i = t; i < T; i += 1024) mx = fmaxf(mx, lg[i]);
    red[t] = mx; __syncthreads();
    for (int s = 512; s; s >>= 1) { if (t < s) red[t] = fmaxf(red[t], red[t + s]); __syncthreads(); }
    float m = red[0]; __syncthreads();
    float sm = 0.f;
    for (int i = t; i < T; i += 1024) sm += expf(lg[i] - m);
    red[t] = sm; __syncthreads();
    for (int s = 512; s; s >>= 1) { if (t < s) red[t] += red[t + s]; __syncthreads(); }
    float inv = 1.f / red[0];
    for (int i = t; i < T; i += 1024) out[i] = expf(lg[i] - m) * inv;
}

// ---------------------------------------------------------------------------
// Launch — dual-stream DAG, fused layer-0, fused seg-sum, fused head dots.
// ---------------------------------------------------------------------------
extern "C" void kernel_launch(void* const* d_in, const int* in_sizes, int n_in,
                              void* d_out, int out_size)
{
    const float* x     = (const float*)d_in[0];
    const float* ea    = (const float*)d_in[1];
    const int*   ei    = (const int*)  d_in[2];
    const int*   nbr   = (const int*)  d_in[3];
    const float* Wz_w  = (const float*)d_in[4];
    const float* Wz_b  = (const float*)d_in[5];
    const float* Wr_w  = (const float*)d_in[6];
    const float* Wr_b  = (const float*)d_in[7];
    const float* W_w   = (const float*)d_in[8];
    const float* U_w   = (const float*)d_in[9];
    const float* U_b   = (const float*)d_in[10];
    const float* mlp_w = (const float*)d_in[11];
    const float* mlp_b = (const float*)d_in[12];
    const float* nc1_w = (const float*)d_in[13];
    const float* nc1_b = (const float*)d_in[14];
    const float* nc2_w = (const float*)d_in[15];
    const float* nc2_b = (const float*)d_in[16];
    const float* ec1_w = (const float*)d_in[17];
    const float* ec1_b = (const float*)d_in[18];
    const float* ec2_w = (const float*)d_in[19];
    const float* ec2_b = (const float*)d_in[20];

    const int n  = in_sizes[0] / 128;
    const int E  = in_sizes[1] / 32;
    const int Ne = E / 2;
    const int* tgt = ei + E;

    float *feats, *suv, *zb, *rb, *rd, *msgA, *msgB, *aggr, *xg, *xe, *lg, *wr_, *wl0, *bl0;
    cudaGetSymbolAddress((void**)&feats, g_feats);
    cudaGetSymbolAddress((void**)&suv,  g_suv);
    cudaGetSymbolAddress((void**)&zb,   g_zbuf);
    cudaGetSymbolAddress((void**)&rb,   g_rbuf);
    cudaGetSymbolAddress((void**)&rd,   g_rd);
    cudaGetSymbolAddress((void**)&msgA, g_msgA);
    cudaGetSymbolAddress((void**)&msgB, g_msgB);
    cudaGetSymbolAddress((void**)&aggr, g_aggr);
    cudaGetSymbolAddress((void**)&xg,   g_xg);
    cudaGetSymbolAddress((void**)&xe,   g_xe);
    cudaGetSymbolAddress((void**)&lg,   g_logits);
    cudaGetSymbolAddress((void**)&wr_,  g_wrnd);
    cudaGetSymbolAddress((void**)&wl0,  g_wl0);
    cudaGetSymbolAddress((void**)&bl0,  g_bl0);

    static cudaStream_t s1 = nullptr;
    static cudaEvent_t  ev[16];
    if (!s1) {
        cudaStreamCreateWithFlags(&s1, cudaStreamNonBlocking);
        for (int i = 0; i < 16; i++)
            cudaEventCreateWithFlags(&ev[i], cudaEventDisableTiming);
    }

    cudaFuncSetAttribute(gemm_tc<0,160,256>, cudaFuncAttributeMaxDynamicSharedMemorySize, SMEM_BYTES);
    cudaFuncSetAttribute(gemm_tc<2,160,256>, cudaFuncAttributeMaxDynamicSharedMemorySize, SMEM_BYTES);
    cudaFuncSetAttribute(gemm_tc<5,160,256>, cudaFuncAttributeMaxDynamicSharedMemorySize, SMEM_BYTES);
    cudaFuncSetAttribute(gemm_tc<7,160,0>,   cudaFuncAttributeMaxDynamicSharedMemorySize, SMEM_BYTES);
    cudaFuncSetAttribute(gemm_tc<1,128,256>, cudaFuncAttributeMaxDynamicSharedMemorySize, SMEM_BYTES);
    cudaFuncSetAttribute(gemm_tc<6,256,0>,   cudaFuncAttributeMaxDynamicSharedMemorySize, SMEM_BYTES);
    cudaFuncSetAttribute(gemm_tc<6,512,0>,   cudaFuncAttributeMaxDynamicSharedMemorySize, SMEM_BYTES);

    const float* rWz  = wr_ + W_OFF[0];
    const float* rWr  = wr_ + W_OFF[1];
    const float* rW   = wr_ + W_OFF[2];
    const float* rU   = wr_ + W_OFF[3];
    const float* rmlp = wr_ + W_OFF[4];
    const float* rnc1 = wr_ + W_OFF[5];
    const float* rec1 = wr_ + W_OFF[6];

    const int TPB = 256;
    const int gE64 = (E * 64 + TPB - 1) / TPB;
    dim3 gg(2, (E + 127) / 128);

    // ---- prologue: fork first, then s1 work ----
    cudaEventRecord(ev[0], 0);
    cudaStreamWaitEvent(s1, ev[0], 0);
    roundw_k<<<dim3(416, 7), 256, 0, s1>>>(Wz_w, Wr_w, W_w, U_w, mlp_w, nc1_w, ec1_w, wr_);
    il0_k<<<80, 256, 0, s1>>>(Wz_w, W_w, Wz_b, U_b, wl0, bl0);
    cudaEventRecord(ev[1], s1);

    feats_k<<<(E * 40 + TPB - 1) / TPB, TPB>>>(x, ea, tgt, feats, E);
    cudaMemsetAsync(aggr, 0, (size_t)n * 256 * sizeof(float));
    initlg_k<<<(n + Ne + TPB - 1) / TPB, TPB>>>(lg, nc2_b, ec2_b, n, n + Ne);

    cudaStreamWaitEvent(0, ev[1], 0);

    // ---- layer 0: ONE fused GEMM (interleaved z/m columns) ----
    dim3 gl0(4, (E + 127) / 128);
    gemm_tc<7,160,0><<<gl0, 256, SMEM_BYTES>>>(
        feats, nullptr, wl0, 160, nullptr, 0,
        bl0, nullptr, nullptr, nullptr, msgA, E, 512);
    cudaEventRecord(ev[2], 0);
    cudaStreamWaitEvent(s1, ev[2], 0);

    float* msg_in  = msgA;
    float* msg_out = msgB;
    int ie = 3;
    for (int l = 1; l < 4; l++) {
        const float* wz = rWz + (size_t)l * 256 * 416;
        const float* wrr= rWr + (size_t)l * 256 * 416;
        const float* ww = rW  + (size_t)l * 256 * 160;
        const float* uw = rU  + (size_t)l * 256 * 256;

        // s1: r-gemm -> rdash
        gemm_tc<0,160,256><<<gg, 256, SMEM_BYTES, s1>>>(
            feats, msg_in, wrr, 416, wrr + 160, 416,
            Wr_b + l * 256, nullptr, nullptr, nullptr, rb, E, 256);
        rdash_k<<<gE64, TPB, 0, s1>>>(rb, msg_in, nbr, rd, E);
        cudaEventRecord(ev[ie], s1);

        // s0: gather -> z-gemm
        gather_s_k<<<gE64, TPB>>>(msg_in, nbr, suv, E);
        gemm_tc<0,160,256><<<gg, 256, SMEM_BYTES>>>(
            feats, suv, wz, 416, wz + 160, 416,
            Wz_b + l * 256, nullptr, nullptr, nullptr, zb, E, 256);

        // join: m-gemm on s0 (last layer fuses segment-sum into aggr)
        cudaStreamWaitEvent(0, ev[ie], 0); ie++;
        if (l < 3) {
            gemm_tc<2,160,256><<<gg, 256, SMEM_BYTES>>>(
                feats, rd, ww, 160, uw, 256,
                U_b + l * 256, zb, suv, nullptr, msg_out, E, 256);
        } else {
            gemm_tc<5,160,256><<<gg, 256, SMEM_BYTES>>>(
                feats, rd, ww, 160, uw, 256,
                U_b + l * 256, zb, suv, tgt, aggr, E, 256);
        }
        cudaEventRecord(ev[ie], 0);
        cudaStreamWaitEvent(s1, ev[ie], 0); ie++;

        float* tmp = msg_in; msg_in = msg_out; msg_out = tmp;
    }

    // ---- readout: node head (s0) || edge head (s1) ----
    dim3 gx(2, (n + 127) / 128);
    gemm_tc<1,128,256><<<gx, 256, SMEM_BYTES>>>(
        x, aggr, rmlp, 384, rmlp + 128, 384,
        mlp_b, nullptr, nullptr, nullptr, xg, n, 256);
    cudaEventRecord(ev[ie], 0);
    cudaStreamWaitEvent(s1, ev[ie], 0); ie++;

    // s1: edge branch (fused 512->1 dot into logits)
    xedge_k<<<(Ne * 128 + TPB - 1) / TPB, TPB, 0, s1>>>(xg, ei, xe, E, Ne);
    dim3 g2(4, (Ne + 127) / 128);
    gemm_tc<6,512,0><<<g2, 256, SMEM_BYTES, s1>>>(
        xe, nullptr, rec1, 512, nullptr, 0,
        ec1_b, nullptr, ec2_w, nullptr, lg + n, Ne, 512);
    cudaEventRecord(ev[ie], s1);

    // s0: node branch (fused 512->1 dot into logits)
    dim3 g1(4, (n + 127) / 128);
    gemm_tc<6,256,0><<<g1, 256, SMEM_BYTES>>>(
        xg, nullptr, rnc1, 256, nullptr, 0,
        nc1_b, nullptr, nc2_w, nullptr, lg, n, 512);

    // join + softmax
    cudaStreamWaitEvent(0, ev[ie], 0); ie++;
    softmax_k<<<1, 1024>>>(lg, (float*)d_out, n + Ne);
}